// round 7
// baseline (speedup 1.0000x reference)
#include <cuda_runtime.h>
#include <cstdint>

// Problem constants
#define N_HEAD   16
#define C_EMBD   1024
#define HEAD_D   64
#define CHUNK    64
#define BATCH    4
#define SEQ      4096
#define M_TOK    (BATCH * SEQ)          // 16384 tokens
#define F_QKV    (3 * C_EMBD)           // 3072

// Scratch buffers (no cudaMalloc allowed anywhere)
__device__ float g_qkv[M_TOK * F_QKV];  // [16384, 3072]  ~201 MB
__device__ float g_y[M_TOK * C_EMBD];   // [16384, 1024]  ~67 MB

typedef unsigned long long ull;

// Packed f32x2 helpers (Blackwell sm_100+: only reachable via PTX)
__device__ __forceinline__ ull pack2(float x, float y) {
    ull r;
    asm("mov.b64 %0, {%1, %2};" : "=l"(r) : "f"(x), "f"(y));
    return r;
}
__device__ __forceinline__ void fma2(ull &c, ull a, ull b) {
    asm("fma.rn.f32x2 %0, %1, %2, %3;" : "=l"(c) : "l"(a), "l"(b), "l"(c));
}

// ----------------------------------------------------------------------------
// NT SGEMM: C[m,n] = sum_k A[m,K+k] * B[n,K+k]
// 128x128 block tile, BK=16, 256 threads, 8x8 register tile per thread,
// accumulators packed in f32x2 pairs along N. Global->register prefetch of
// the next K-tile overlaps LDG latency with the 16-step FFMA inner loop.
// Requires: M,N % 128 == 0, K % 16 == 0.
// ----------------------------------------------------------------------------
__global__ __launch_bounds__(256) void sgemm_nt(const float* __restrict__ A,
                                                const float* __restrict__ B,
                                                float* __restrict__ C,
                                                int M, int N, int K) {
    __shared__ float As[16][128];
    __shared__ float Bs[16][128];

    const int tid = threadIdx.x;
    const int tx = tid & 15;        // 0..15 -> N sub-tile
    const int ty = tid >> 4;        // 0..15 -> M sub-tile
    const int bx = blockIdx.x;
    const int by = blockIdx.y;

    // Global load mapping: 128 rows x 16 cols, 2 threads per row (8 floats each)
    const int lr = tid >> 1;                // 0..127
    const int lc = (tid & 1) * 8;           // 0 or 8
    const float* Ag = A + (size_t)(by * 128 + lr) * K + lc;
    const float* Bg = B + (size_t)(bx * 128 + lr) * K + lc;

    ull acc[8][4];
#pragma unroll
    for (int i = 0; i < 8; i++)
#pragma unroll
        for (int j = 0; j < 4; j++) acc[i][j] = 0ull;

    // Prefetch first K-tile into registers
    float4 a0 = *(const float4*)(Ag);
    float4 a1 = *(const float4*)(Ag + 4);
    float4 b0 = *(const float4*)(Bg);
    float4 b1 = *(const float4*)(Bg + 4);

    for (int k0 = 0; k0 < K; k0 += 16) {
        // Deposit current tile into smem
        As[lc + 0][lr] = a0.x; As[lc + 1][lr] = a0.y;
        As[lc + 2][lr] = a0.z; As[lc + 3][lr] = a0.w;
        As[lc + 4][lr] = a1.x; As[lc + 5][lr] = a1.y;
        As[lc + 6][lr] = a1.z; As[lc + 7][lr] = a1.w;
        Bs[lc + 0][lr] = b0.x; Bs[lc + 1][lr] = b0.y;
        Bs[lc + 2][lr] = b0.z; Bs[lc + 3][lr] = b0.w;
        Bs[lc + 4][lr] = b1.x; Bs[lc + 5][lr] = b1.y;
        Bs[lc + 6][lr] = b1.z; Bs[lc + 7][lr] = b1.w;
        __syncthreads();

        // Issue next tile's global loads NOW; latency hidden by inner loop
        if (k0 + 16 < K) {
            a0 = *(const float4*)(Ag + k0 + 16);
            a1 = *(const float4*)(Ag + k0 + 20);
            b0 = *(const float4*)(Bg + k0 + 16);
            b1 = *(const float4*)(Bg + k0 + 20);
        }

#pragma unroll
        for (int kk = 0; kk < 16; kk++) {
            const float4 av0 = *(const float4*)&As[kk][ty * 8];
            const float4 av1 = *(const float4*)&As[kk][ty * 8 + 4];
            const float4 bv0 = *(const float4*)&Bs[kk][tx * 8];
            const float4 bv1 = *(const float4*)&Bs[kk][tx * 8 + 4];

            ull bp[4];
            bp[0] = pack2(bv0.x, bv0.y);
            bp[1] = pack2(bv0.z, bv0.w);
            bp[2] = pack2(bv1.x, bv1.y);
            bp[3] = pack2(bv1.z, bv1.w);

            float as[8] = {av0.x, av0.y, av0.z, av0.w, av1.x, av1.y, av1.z, av1.w};
#pragma unroll
            for (int i = 0; i < 8; i++) {
                ull ap = pack2(as[i], as[i]);
#pragma unroll
                for (int j = 0; j < 4; j++) fma2(acc[i][j], ap, bp[j]);
            }
        }
        __syncthreads();
    }

    // Store: row = by*128 + ty*8 + i, cols bx*128 + tx*8 .. +7
#pragma unroll
    for (int i = 0; i < 8; i++) {
        float* Crow = C + (size_t)(by * 128 + ty * 8 + i) * N + bx * 128 + tx * 8;
        float2 p0 = *(float2*)&acc[i][0];
        float2 p1 = *(float2*)&acc[i][1];
        float2 p2 = *(float2*)&acc[i][2];
        float2 p3 = *(float2*)&acc[i][3];
        *(float4*)(Crow + 0) = make_float4(p0.x, p0.y, p1.x, p1.y);
        *(float4*)(Crow + 4) = make_float4(p2.x, p2.y, p3.x, p3.y);
    }
}

// ----------------------------------------------------------------------------
// Chunked attention: one CTA per (batch, chunk, head).
// Loads q,k (with RoPE) and v into padded smem, computes softmax(q k^T / 8) v.
// smem stride 68 floats: keeps 16B alignment for float4 while avoiding
// stride-64 bank pathologies.
// ----------------------------------------------------------------------------
#define ATT_PAD 68
#define ATT_SMEM_BYTES (4 * 64 * ATT_PAD * 4)

__global__ __launch_bounds__(256) void attn_kernel() {
    extern __shared__ float sm[];
    float* qs = sm;                        // 64 x 68
    float* ks = qs + 64 * ATT_PAD;
    float* vs = ks + 64 * ATT_PAD;
    float* ss = vs + 64 * ATT_PAD;         // scores / probs
    __shared__ float sinv[32];

    const int tid = threadIdx.x;
    const int bid = blockIdx.x;            // 0 .. 4095
    const int h = bid & 15;
    const int n = (bid >> 4) & 63;
    const int b = bid >> 10;

    // inv_freq[i] = 10000^(-i/32)
    if (tid < 32)
        sinv[tid] = __expf(-((float)tid * (1.0f / 32.0f)) * 9.210340371976184f);
    __syncthreads();

    const int tokbase = b * SEQ + n * CHUNK;

    // Load q,k with RoPE: out[i] = x1*c + x2*s ; out[i+32] = -x1*s + x2*c
    for (int e = tid; e < 64 * 32; e += 256) {
        const int s = e >> 5;
        const int i = e & 31;
        const float ang = (float)s * sinv[i];
        float sn, c;
        sincosf(ang, &sn, &c);
        const size_t base = (size_t)(tokbase + s) * F_QKV + h * HEAD_D;
        const float q1 = g_qkv[base + i];
        const float q2 = g_qkv[base + 32 + i];
        qs[s * ATT_PAD + i]      =  q1 * c + q2 * sn;
        qs[s * ATT_PAD + 32 + i] = -q1 * sn + q2 * c;
        const float k1 = g_qkv[base + C_EMBD + i];
        const float k2 = g_qkv[base + C_EMBD + 32 + i];
        ks[s * ATT_PAD + i]      =  k1 * c + k2 * sn;
        ks[s * ATT_PAD + 32 + i] = -k1 * sn + k2 * c;
    }
    // Load v
    for (int e = tid; e < 64 * 64; e += 256) {
        const int s = e >> 6;
        const int dd = e & 63;
        vs[s * ATT_PAD + dd] =
            g_qkv[(size_t)(tokbase + s) * F_QKV + 2 * C_EMBD + h * HEAD_D + dd];
    }
    __syncthreads();

    // scores = q k^T * 0.125 : 4x4 register tile per thread
    {
        const int qrt = (tid >> 4) << 2;   // 0,4,..60
        const int kct = (tid & 15) << 2;   // 0,4,..60
        float acc[4][4];
#pragma unroll
        for (int r = 0; r < 4; r++)
#pragma unroll
            for (int c = 0; c < 4; c++) acc[r][c] = 0.0f;

        for (int i = 0; i < 64; i += 4) {
            float4 qv[4], kv[4];
#pragma unroll
            for (int r = 0; r < 4; r++)
                qv[r] = *(const float4*)&qs[(qrt + r) * ATT_PAD + i];
#pragma unroll
            for (int c = 0; c < 4; c++)
                kv[c] = *(const float4*)&ks[(kct + c) * ATT_PAD + i];
#pragma unroll
            for (int r = 0; r < 4; r++)
#pragma unroll
                for (int c = 0; c < 4; c++)
                    acc[r][c] += qv[r].x * kv[c].x + qv[r].y * kv[c].y +
                                 qv[r].z * kv[c].z + qv[r].w * kv[c].w;
        }
        const float scale = 0.125f;
#pragma unroll
        for (int r = 0; r < 4; r++)
            *(float4*)&ss[(qrt + r) * ATT_PAD + kct] =
                make_float4(acc[r][0] * scale, acc[r][1] * scale,
                            acc[r][2] * scale, acc[r][3] * scale);
    }
    __syncthreads();

    // softmax per row: 4 lanes per row, 16 elems each, shuffle-reduce
    {
        const int row = tid >> 2;
        const int g = tid & 3;
        float loc[16];
        float m = -1e30f;
#pragma unroll
        for (int j = 0; j < 16; j++) {
            loc[j] = ss[row * ATT_PAD + g * 16 + j];
            m = fmaxf(m, loc[j]);
        }
        m = fmaxf(m, __shfl_xor_sync(0xffffffffu, m, 1));
        m = fmaxf(m, __shfl_xor_sync(0xffffffffu, m, 2));
        float sum = 0.0f;
#pragma unroll
        for (int j = 0; j < 16; j++) {
            loc[j] = __expf(loc[j] - m);
            sum += loc[j];
        }
        sum += __shfl_xor_sync(0xffffffffu, sum, 1);
        sum += __shfl_xor_sync(0xffffffffu, sum, 2);
        const float inv = 1.0f / sum;
#pragma unroll
        for (int j = 0; j < 16; j++)
            ss[row * ATT_PAD + g * 16 + j] = loc[j] * inv;
    }
    __syncthreads();

    // y = p @ v : 4x4 register tile per thread, write to g_y
    {
        const int qrt = (tid >> 4) << 2;
        const int ddt = (tid & 15) << 2;
        float acc[4][4];
#pragma unroll
        for (int r = 0; r < 4; r++)
#pragma unroll
            for (int c = 0; c < 4; c++) acc[r][c] = 0.0f;

        for (int kc = 0; kc < 64; kc += 4) {
            float4 pv[4], vv[4];
#pragma unroll
            for (int r = 0; r < 4; r++)
                pv[r] = *(const float4*)&ss[(qrt + r) * ATT_PAD + kc];
#pragma unroll
            for (int m2 = 0; m2 < 4; m2++)
                vv[m2] = *(const float4*)&vs[(kc + m2) * ATT_PAD + ddt];
#pragma unroll
            for (int r = 0; r < 4; r++) {
                acc[r][0] += pv[r].x * vv[0].x + pv[r].y * vv[1].x +
                             pv[r].z * vv[2].x + pv[r].w * vv[3].x;
                acc[r][1] += pv[r].x * vv[0].y + pv[r].y * vv[1].y +
                             pv[r].z * vv[2].y + pv[r].w * vv[3].y;
                acc[r][2] += pv[r].x * vv[0].z + pv[r].y * vv[1].z +
                             pv[r].z * vv[2].z + pv[r].w * vv[3].z;
                acc[r][3] += pv[r].x * vv[0].w + pv[r].y * vv[1].w +
                             pv[r].z * vv[2].w + pv[r].w * vv[3].w;
            }
        }
#pragma unroll
        for (int r = 0; r < 4; r++)
            *(float4*)&g_y[(size_t)(tokbase + qrt + r) * C_EMBD + h * HEAD_D + ddt] =
                make_float4(acc[r][0], acc[r][1], acc[r][2], acc[r][3]);
    }
}

// ----------------------------------------------------------------------------
extern "C" void kernel_launch(void* const* d_in, const int* in_sizes, int n_in,
                              void* d_out, int out_size) {
    const float* x      = (const float*)d_in[0];   // [4,4096,1024]
    const float* w_attn = (const float*)d_in[1];   // [3072,1024]
    const float* w_proj = (const float*)d_in[2];   // [1024,1024]
    float* out = (float*)d_out;                    // [4,4096,1024]

    float* qkv = nullptr;
    float* ybuf = nullptr;
    cudaGetSymbolAddress((void**)&qkv, g_qkv);
    cudaGetSymbolAddress((void**)&ybuf, g_y);

    cudaFuncSetAttribute(attn_kernel,
                         cudaFuncAttributeMaxDynamicSharedMemorySize,
                         ATT_SMEM_BYTES);

    dim3 blk(256);
    // qkv = x @ w_attn^T
    sgemm_nt<<<dim3(F_QKV / 128, M_TOK / 128), blk>>>(x, w_attn, qkv,
                                                      M_TOK, F_QKV, C_EMBD);
    // per-chunk attention (RoPE fused)
    attn_kernel<<<BATCH * (SEQ / CHUNK) * N_HEAD, blk, ATT_SMEM_BYTES>>>();
    // out = y @ w_proj^T
    sgemm_nt<<<dim3(C_EMBD / 128, M_TOK / 128), blk>>>(ybuf, w_proj, out,
                                                       M_TOK, C_EMBD, C_EMBD);
}

// round 10
// speedup vs baseline: 2.3118x; 2.3118x over previous
#include <cuda_runtime.h>
#include <cstdint>

// Problem constants
#define N_HEAD   16
#define C_EMBD   1024
#define HEAD_D   64
#define CHUNK    64
#define BATCH    4
#define SEQ      4096
#define M_TOK    (BATCH * SEQ)          // 16384 tokens
#define F_QKV    (3 * C_EMBD)           // 3072

// Scratch buffers (no cudaMalloc allowed anywhere)
__device__ float g_qkv[M_TOK * F_QKV];  // [16384, 3072]  ~201 MB
__device__ float g_y[M_TOK * C_EMBD];   // [16384, 1024]  ~67 MB

__device__ __forceinline__ uint32_t f2tf32(float x) {
    uint32_t r;
    asm("cvt.rna.tf32.f32 %0, %1;" : "=r"(r) : "f"(x));
    return r;
}

// m16n8k8 tf32 mma: D(16x8,f32) += A(16x8,row) * B(8x8,col)
__device__ __forceinline__ void mma_tf32(float* d, const uint32_t* a,
                                         const uint32_t* b) {
    asm volatile(
        "mma.sync.aligned.m16n8k8.row.col.f32.tf32.tf32.f32 "
        "{%0,%1,%2,%3}, {%4,%5,%6,%7}, {%8,%9}, {%0,%1,%2,%3};"
        : "+f"(d[0]), "+f"(d[1]), "+f"(d[2]), "+f"(d[3])
        : "r"(a[0]), "r"(a[1]), "r"(a[2]), "r"(a[3]), "r"(b[0]), "r"(b[1]));
}

// ============================================================================
// NT GEMM via mma.sync tf32: C[m,n] = sum_k A[m,k] * B[n,k]
// 128x128 CTA tile, BK=32, 256 threads = 8 warps in 2(m) x 4(n) grid,
// 64x32 warp tile = 4x4 m16n8k8 fragments. Double-buffered smem (pad 36),
// register prefetch of next K-chunk, cvt.rna.tf32 at STS time.
// Requires M,N % 128 == 0, K % 32 == 0.
// ============================================================================
#define PADK 36
#define TILE_U (128 * PADK)                 // uint32 per matrix per buffer
#define G_SMEM_BYTES (4 * TILE_U * 4)       // 2 bufs x (A,B) x 128x36 x 4B

__global__ __launch_bounds__(256) void gemm_mma(const float* __restrict__ A,
                                                const float* __restrict__ B,
                                                float* __restrict__ C,
                                                int N, int K) {
    extern __shared__ uint32_t sm_u[];
    uint32_t* Asm = sm_u;                   // [2][128][36]
    uint32_t* Bsm = sm_u + 2 * TILE_U;      // [2][128][36]

    const int tid = threadIdx.x;
    const int lane = tid & 31;
    const int wid = tid >> 5;
    const int warp_m = wid >> 2;            // 0..1 -> 64 rows
    const int warp_n = wid & 3;             // 0..3 -> 32 cols
    const int bx = blockIdx.x;
    const int by = blockIdx.y;

    // Global load mapping: 2 threads per row, 16 floats each (4 float4)
    const int r = tid >> 1;
    const int half = tid & 1;
    const float* Ag = A + (size_t)(by * 128 + r) * K + half * 16;
    const float* Bg = B + (size_t)(bx * 128 + r) * K + half * 16;
    const uint32_t stsoff = r * PADK + half * 16;

    float acc[4][4][4];
#pragma unroll
    for (int i = 0; i < 4; i++)
#pragma unroll
        for (int j = 0; j < 4; j++)
#pragma unroll
            for (int e = 0; e < 4; e++) acc[i][j][e] = 0.0f;

    const int r0 = lane >> 2;               // fragment row within 8
    const int c0 = lane & 3;                // fragment col within 4

    // Prefetch chunk 0
    float4 pa[4], pb[4];
#pragma unroll
    for (int j = 0; j < 4; j++) {
        pa[j] = *(const float4*)(Ag + j * 4);
        pb[j] = *(const float4*)(Bg + j * 4);
    }
    // Stage chunk 0 into buffer 0
#pragma unroll
    for (int j = 0; j < 4; j++) {
        *(uint4*)(Asm + stsoff + j * 4) = make_uint4(
            f2tf32(pa[j].x), f2tf32(pa[j].y), f2tf32(pa[j].z), f2tf32(pa[j].w));
        *(uint4*)(Bsm + stsoff + j * 4) = make_uint4(
            f2tf32(pb[j].x), f2tf32(pb[j].y), f2tf32(pb[j].z), f2tf32(pb[j].w));
    }
    __syncthreads();

    const int nch = K >> 5;
    for (int c = 0; c < nch; c++) {
        const int s = c & 1;
        const uint32_t* Ab = Asm + s * TILE_U;
        const uint32_t* Bb = Bsm + s * TILE_U;

        // Prefetch chunk c+1 into registers (latency hidden by compute)
        if (c + 1 < nch) {
#pragma unroll
            for (int j = 0; j < 4; j++) {
                pa[j] = *(const float4*)(Ag + (c + 1) * 32 + j * 4);
                pb[j] = *(const float4*)(Bg + (c + 1) * 32 + j * 4);
            }
        }

        // 4 k-steps of 8
#pragma unroll
        for (int ks = 0; ks < 4; ks++) {
            const int k0 = ks * 8;
            uint32_t af[4][4], bf[4][2];
#pragma unroll
            for (int mf = 0; mf < 4; mf++) {
                const uint32_t base =
                    (warp_m * 64 + mf * 16 + r0) * PADK + k0 + c0;
                af[mf][0] = Ab[base];
                af[mf][1] = Ab[base + 8 * PADK];
                af[mf][2] = Ab[base + 4];
                af[mf][3] = Ab[base + 8 * PADK + 4];
            }
#pragma unroll
            for (int nf = 0; nf < 4; nf++) {
                const uint32_t base =
                    (warp_n * 32 + nf * 8 + r0) * PADK + k0 + c0;
                bf[nf][0] = Bb[base];
                bf[nf][1] = Bb[base + 4];
            }
#pragma unroll
            for (int mf = 0; mf < 4; mf++)
#pragma unroll
                for (int nf = 0; nf < 4; nf++)
                    mma_tf32(acc[mf][nf], af[mf], bf[nf]);
        }

        // Stage chunk c+1 into the other buffer
        if (c + 1 < nch) {
            uint32_t* An = Asm + (1 - s) * TILE_U;
            uint32_t* Bn = Bsm + (1 - s) * TILE_U;
#pragma unroll
            for (int j = 0; j < 4; j++) {
                *(uint4*)(An + stsoff + j * 4) = make_uint4(
                    f2tf32(pa[j].x), f2tf32(pa[j].y),
                    f2tf32(pa[j].z), f2tf32(pa[j].w));
                *(uint4*)(Bn + stsoff + j * 4) = make_uint4(
                    f2tf32(pb[j].x), f2tf32(pb[j].y),
                    f2tf32(pb[j].z), f2tf32(pb[j].w));
            }
            __syncthreads();
        }
    }

    // Epilogue: fragment layout c0,c1 at (row, 2c), (row, 2c+1); c2,c3 at row+8
    const int mrow = by * 128 + warp_m * 64 + r0;
    const int ncol = bx * 128 + warp_n * 32 + c0 * 2;
#pragma unroll
    for (int mf = 0; mf < 4; mf++) {
#pragma unroll
        for (int nf = 0; nf < 4; nf++) {
            float* p0 = C + (size_t)(mrow + mf * 16) * N + ncol + nf * 8;
            float* p1 = p0 + 8 * N;
            *(float2*)p0 = make_float2(acc[mf][nf][0], acc[mf][nf][1]);
            *(float2*)p1 = make_float2(acc[mf][nf][2], acc[mf][nf][3]);
        }
    }
}

// ----------------------------------------------------------------------------
// Chunked attention: one CTA per (batch, chunk, head). Full fp32.
// ----------------------------------------------------------------------------
#define ATT_PAD 68
#define ATT_SMEM_BYTES (4 * 64 * ATT_PAD * 4)

__global__ __launch_bounds__(256) void attn_kernel() {
    extern __shared__ float sm[];
    float* qs = sm;                        // 64 x 68
    float* ks = qs + 64 * ATT_PAD;
    float* vs = ks + 64 * ATT_PAD;
    float* ss = vs + 64 * ATT_PAD;         // scores / probs
    __shared__ float sinv[32];

    const int tid = threadIdx.x;
    const int bid = blockIdx.x;            // 0 .. 4095
    const int h = bid & 15;
    const int n = (bid >> 4) & 63;
    const int b = bid >> 10;

    if (tid < 32)
        sinv[tid] = __expf(-((float)tid * (1.0f / 32.0f)) * 9.210340371976184f);
    __syncthreads();

    const int tokbase = b * SEQ + n * CHUNK;

    for (int e = tid; e < 64 * 32; e += 256) {
        const int s = e >> 5;
        const int i = e & 31;
        const float ang = (float)s * sinv[i];
        float sn, c;
        sincosf(ang, &sn, &c);
        const size_t base = (size_t)(tokbase + s) * F_QKV + h * HEAD_D;
        const float q1 = g_qkv[base + i];
        const float q2 = g_qkv[base + 32 + i];
        qs[s * ATT_PAD + i]      =  q1 * c + q2 * sn;
        qs[s * ATT_PAD + 32 + i] = -q1 * sn + q2 * c;
        const float k1 = g_qkv[base + C_EMBD + i];
        const float k2 = g_qkv[base + C_EMBD + 32 + i];
        ks[s * ATT_PAD + i]      =  k1 * c + k2 * sn;
        ks[s * ATT_PAD + 32 + i] = -k1 * sn + k2 * c;
    }
    for (int e = tid; e < 64 * 64; e += 256) {
        const int s = e >> 6;
        const int dd = e & 63;
        vs[s * ATT_PAD + dd] =
            g_qkv[(size_t)(tokbase + s) * F_QKV + 2 * C_EMBD + h * HEAD_D + dd];
    }
    __syncthreads();

    {
        const int qrt = (tid >> 4) << 2;
        const int kct = (tid & 15) << 2;
        float acc[4][4];
#pragma unroll
        for (int r = 0; r < 4; r++)
#pragma unroll
            for (int c = 0; c < 4; c++) acc[r][c] = 0.0f;

        for (int i = 0; i < 64; i += 4) {
            float4 qv[4], kv[4];
#pragma unroll
            for (int r = 0; r < 4; r++)
                qv[r] = *(const float4*)&qs[(qrt + r) * ATT_PAD + i];
#pragma unroll
            for (int c = 0; c < 4; c++)
                kv[c] = *(const float4*)&ks[(kct + c) * ATT_PAD + i];
#pragma unroll
            for (int r = 0; r < 4; r++)
#pragma unroll
                for (int c = 0; c < 4; c++)
                    acc[r][c] += qv[r].x * kv[c].x + qv[r].y * kv[c].y +
                                 qv[r].z * kv[c].z + qv[r].w * kv[c].w;
        }
        const float scale = 0.125f;
#pragma unroll
        for (int r = 0; r < 4; r++)
            *(float4*)&ss[(qrt + r) * ATT_PAD + kct] =
                make_float4(acc[r][0] * scale, acc[r][1] * scale,
                            acc[r][2] * scale, acc[r][3] * scale);
    }
    __syncthreads();

    {
        const int row = tid >> 2;
        const int g = tid & 3;
        float loc[16];
        float m = -1e30f;
#pragma unroll
        for (int j = 0; j < 16; j++) {
            loc[j] = ss[row * ATT_PAD + g * 16 + j];
            m = fmaxf(m, loc[j]);
        }
        m = fmaxf(m, __shfl_xor_sync(0xffffffffu, m, 1));
        m = fmaxf(m, __shfl_xor_sync(0xffffffffu, m, 2));
        float sum = 0.0f;
#pragma unroll
        for (int j = 0; j < 16; j++) {
            loc[j] = __expf(loc[j] - m);
            sum += loc[j];
        }
        sum += __shfl_xor_sync(0xffffffffu, sum, 1);
        sum += __shfl_xor_sync(0xffffffffu, sum, 2);
        const float inv = 1.0f / sum;
#pragma unroll
        for (int j = 0; j < 16; j++)
            ss[row * ATT_PAD + g * 16 + j] = loc[j] * inv;
    }
    __syncthreads();

    {
        const int qrt = (tid >> 4) << 2;
        const int ddt = (tid & 15) << 2;
        float acc[4][4];
#pragma unroll
        for (int r = 0; r < 4; r++)
#pragma unroll
            for (int c = 0; c < 4; c++) acc[r][c] = 0.0f;

        for (int kc = 0; kc < 64; kc += 4) {
            float4 pv[4], vv[4];
#pragma unroll
            for (int r = 0; r < 4; r++)
                pv[r] = *(const float4*)&ss[(qrt + r) * ATT_PAD + kc];
#pragma unroll
            for (int m2 = 0; m2 < 4; m2++)
                vv[m2] = *(const float4*)&vs[(kc + m2) * ATT_PAD + ddt];
#pragma unroll
            for (int r = 0; r < 4; r++) {
                acc[r][0] += pv[r].x * vv[0].x + pv[r].y * vv[1].x +
                             pv[r].z * vv[2].x + pv[r].w * vv[3].x;
                acc[r][1] += pv[r].x * vv[0].y + pv[r].y * vv[1].y +
                             pv[r].z * vv[2].y + pv[r].w * vv[3].y;
                acc[r][2] += pv[r].x * vv[0].z + pv[r].y * vv[1].z +
                             pv[r].z * vv[2].z + pv[r].w * vv[3].z;
                acc[r][3] += pv[r].x * vv[0].w + pv[r].y * vv[1].w +
                             pv[r].z * vv[2].w + pv[r].w * vv[3].w;
            }
        }
#pragma unroll
        for (int r = 0; r < 4; r++)
            *(float4*)&g_y[(size_t)(tokbase + qrt + r) * C_EMBD + h * HEAD_D + ddt] =
                make_float4(acc[r][0], acc[r][1], acc[r][2], acc[r][3]);
    }
}

// ----------------------------------------------------------------------------
extern "C" void kernel_launch(void* const* d_in, const int* in_sizes, int n_in,
                              void* d_out, int out_size) {
    const float* x      = (const float*)d_in[0];   // [4,4096,1024]
    const float* w_attn = (const float*)d_in[1];   // [3072,1024]
    const float* w_proj = (const float*)d_in[2];   // [1024,1024]
    float* out = (float*)d_out;                    // [4,4096,1024]

    float* qkv = nullptr;
    float* ybuf = nullptr;
    cudaGetSymbolAddress((void**)&qkv, g_qkv);
    cudaGetSymbolAddress((void**)&ybuf, g_y);

    cudaFuncSetAttribute(gemm_mma,
                         cudaFuncAttributeMaxDynamicSharedMemorySize,
                         G_SMEM_BYTES);
    cudaFuncSetAttribute(attn_kernel,
                         cudaFuncAttributeMaxDynamicSharedMemorySize,
                         ATT_SMEM_BYTES);

    dim3 blk(256);
    // qkv = x @ w_attn^T
    gemm_mma<<<dim3(F_QKV / 128, M_TOK / 128), blk, G_SMEM_BYTES>>>(
        x, w_attn, qkv, F_QKV, C_EMBD);
    // per-chunk attention (RoPE fused)
    attn_kernel<<<BATCH * (SEQ / CHUNK) * N_HEAD, blk, ATT_SMEM_BYTES>>>();
    // out = y @ w_proj^T
    gemm_mma<<<dim3(C_EMBD / 128, M_TOK / 128), blk, G_SMEM_BYTES>>>(
        ybuf, w_proj, out, C_EMBD, C_EMBD);
}

// round 14
// speedup vs baseline: 2.7180x; 1.1757x over previous
#include <cuda_runtime.h>
#include <cstdint>

// Problem constants
#define N_HEAD   16
#define C_EMBD   1024
#define HEAD_D   64
#define CHUNK    64
#define BATCH    4
#define SEQ      4096
#define M_TOK    (BATCH * SEQ)          // 16384 tokens
#define F_QKV    (3 * C_EMBD)           // 3072

// Scratch buffers (no cudaMalloc allowed anywhere)
__device__ __align__(16) float    g_qkv[M_TOK * F_QKV];   // fp32 qkv   ~201 MB
__device__ __align__(16) uint32_t g_xa[M_TOK * C_EMBD];   // x   as tf32  64 MB
__device__ __align__(16) uint32_t g_wa[F_QKV * C_EMBD];   // w_attn tf32  12 MB
__device__ __align__(16) uint32_t g_wp[C_EMBD * C_EMBD];  // w_proj tf32   4 MB
__device__ __align__(16) uint32_t g_ya[M_TOK * C_EMBD];   // attn out tf32 64 MB

__device__ __forceinline__ uint32_t f2tf32(float x) {
    uint32_t r;
    asm("cvt.rna.tf32.f32 %0, %1;" : "=r"(r) : "f"(x));
    return r;
}
__device__ __forceinline__ uint32_t smem_u32(const void* p) {
    uint32_t a;
    asm("{ .reg .u64 t; cvta.to.shared.u64 t, %1; cvt.u32.u64 %0, t; }"
        : "=r"(a) : "l"(p));
    return a;
}
// m16n8k8 tf32 mma: D(16x8,f32) += A(16x8,row) * B(8x8,col)
__device__ __forceinline__ void mma_tf32(float* d, const uint32_t* a,
                                         uint32_t b0, uint32_t b1) {
    asm volatile(
        "mma.sync.aligned.m16n8k8.row.col.f32.tf32.tf32.f32 "
        "{%0,%1,%2,%3}, {%4,%5,%6,%7}, {%8,%9}, {%0,%1,%2,%3};"
        : "+f"(d[0]), "+f"(d[1]), "+f"(d[2]), "+f"(d[3])
        : "r"(a[0]), "r"(a[1]), "r"(a[2]), "r"(a[3]), "r"(b0), "r"(b1));
}

// ============================================================================
// Elementwise fp32 -> tf32(rna) conversion (vectorized)
// ============================================================================
__global__ __launch_bounds__(256) void cvt_tf32(const float4* __restrict__ in,
                                                uint4* __restrict__ out, int n4) {
    int i = blockIdx.x * blockDim.x + threadIdx.x;
    if (i < n4) {
        float4 v = in[i];
        out[i] = make_uint4(f2tf32(v.x), f2tf32(v.y), f2tf32(v.z), f2tf32(v.w));
    }
}

// ============================================================================
// NT GEMM via mma.sync tf32, pre-converted inputs, cp.async 3-stage pipeline.
// C[m,n] = sum_k A[m,k]*B[n,k];  A:[M,K] u32, B:[N,K] u32, C fp32.
// CTA tile 128x256, BK=32; 8 warps (2m x 4n), warp tile 64x64.
// Requires M%128==0, N%256==0, K%32==0.
// ============================================================================
#define BM 128
#define BN 256
#define PADK 36
#define A_STG (BM * PADK)               // 4608 u32
#define B_STG (BN * PADK)               // 9216 u32
#define STG_U (A_STG + B_STG)           // 13824 u32 = 55296 B
#define STAGES 3
#define G_SMEM_BYTES (STAGES * STG_U * 4)   // 162 KB

__global__ __launch_bounds__(256, 1) void gemm_mma(const uint32_t* __restrict__ A,
                                                   const uint32_t* __restrict__ B,
                                                   float* __restrict__ C,
                                                   int N, int K) {
    extern __shared__ uint32_t smu[];
    const uint32_t sbase = smem_u32(smu);
    const int tid = threadIdx.x;
    const int lane = tid & 31;
    const int wid = tid >> 5;
    const int warp_m = wid & 1;          // 0..1 -> 64 rows
    const int warp_n = wid >> 1;         // 0..3 -> 64 cols
    const int bx = blockIdx.x;
    const int by = blockIdx.y;
    const int r0 = lane >> 2;            // 0..7
    const int c0 = lane & 3;             // 0..3

    const uint32_t* Agp = A + (size_t)(by * BM) * K;
    const uint32_t* Bgp = B + (size_t)(bx * BN) * K;

    // Issue async copy of K-chunk c into stage s (A: 4 segs/thread, B: 8)
    auto issue_copy = [&](int c, int s) {
        const uint32_t so = (uint32_t)(s * STG_U) * 4;
#pragma unroll
        for (int i = 0; i < 4; i++) {
            const int seg = tid + i * 256;          // 0..1023
            const int row = seg >> 3, sg = seg & 7;
            const uint32_t dst = sbase + so + (uint32_t)(row * PADK + sg * 4) * 4;
            const uint32_t* src = Agp + (size_t)row * K + c * 32 + sg * 4;
            asm volatile("cp.async.cg.shared.global [%0], [%1], 16;"
                         :: "r"(dst), "l"(src));
        }
#pragma unroll
        for (int i = 0; i < 8; i++) {
            const int seg = tid + i * 256;          // 0..2047
            const int row = seg >> 3, sg = seg & 7;
            const uint32_t dst =
                sbase + so + (uint32_t)(A_STG + row * PADK + sg * 4) * 4;
            const uint32_t* src = Bgp + (size_t)row * K + c * 32 + sg * 4;
            asm volatile("cp.async.cg.shared.global [%0], [%1], 16;"
                         :: "r"(dst), "l"(src));
        }
        asm volatile("cp.async.commit_group;");
    };

    float acc[4][8][4];
#pragma unroll
    for (int mf = 0; mf < 4; mf++)
#pragma unroll
        for (int nf = 0; nf < 8; nf++)
#pragma unroll
            for (int e = 0; e < 4; e++) acc[mf][nf][e] = 0.0f;

    const int nch = K >> 5;
    issue_copy(0, 0);
    issue_copy(1, 1);

    for (int c = 0; c < nch; c++) {
        const int s = c % STAGES;
        if (c + 2 < nch) {
            asm volatile("cp.async.wait_group 1;" ::: "memory");
        } else {
            asm volatile("cp.async.wait_group 0;" ::: "memory");
        }
        __syncthreads();   // chunk c visible; all warps done reading stage (c-1)%3
        if (c + 2 < nch) issue_copy(c + 2, (c + 2) % STAGES);

        const uint32_t* As = smu + s * STG_U;
        const uint32_t* Bs = As + A_STG;

#pragma unroll
        for (int ks = 0; ks < 4; ks++) {
            const int k0 = ks * 8;
            uint32_t af[4][4];
#pragma unroll
            for (int mf = 0; mf < 4; mf++) {
                const int base = (warp_m * 64 + mf * 16 + r0) * PADK + k0 + c0;
                af[mf][0] = As[base];
                af[mf][1] = As[base + 8 * PADK];
                af[mf][2] = As[base + 4];
                af[mf][3] = As[base + 8 * PADK + 4];
            }
#pragma unroll
            for (int nf = 0; nf < 8; nf++) {
                const int base = (warp_n * 64 + nf * 8 + r0) * PADK + k0 + c0;
                const uint32_t b0 = Bs[base];
                const uint32_t b1 = Bs[base + 4];
#pragma unroll
                for (int mf = 0; mf < 4; mf++)
                    mma_tf32(acc[mf][nf], af[mf], b0, b1);
            }
        }
    }

    // Epilogue: c{0,1} at (row, 2c0), c{2,3} at (row+8, 2c0)
    const int mrow = by * BM + warp_m * 64 + r0;
    const int ncol = bx * BN + warp_n * 64 + c0 * 2;
#pragma unroll
    for (int mf = 0; mf < 4; mf++) {
#pragma unroll
        for (int nf = 0; nf < 8; nf++) {
            float* p0 = C + (size_t)(mrow + mf * 16) * N + ncol + nf * 8;
            float* p1 = p0 + 8 * N;
            *(float2*)p0 = make_float2(acc[mf][nf][0], acc[mf][nf][1]);
            *(float2*)p1 = make_float2(acc[mf][nf][2], acc[mf][nf][3]);
        }
    }
}

// ----------------------------------------------------------------------------
// Chunked attention: one CTA per (batch, chunk, head). Full fp32 math,
// output written directly as tf32(rna) u32 for the projection GEMM.
// ----------------------------------------------------------------------------
#define ATT_PAD 68
#define ATT_SMEM_BYTES (4 * 64 * ATT_PAD * 4)

__global__ __launch_bounds__(256) void attn_kernel() {
    extern __shared__ float sm[];
    float* qs = sm;                        // 64 x 68
    float* ks = qs + 64 * ATT_PAD;
    float* vs = ks + 64 * ATT_PAD;
    float* ss = vs + 64 * ATT_PAD;         // scores / probs
    __shared__ float sinv[32];

    const int tid = threadIdx.x;
    const int bid = blockIdx.x;            // 0 .. 4095
    const int h = bid & 15;
    const int n = (bid >> 4) & 63;
    const int b = bid >> 10;

    if (tid < 32)
        sinv[tid] = __expf(-((float)tid * (1.0f / 32.0f)) * 9.210340371976184f);
    __syncthreads();

    const int tokbase = b * SEQ + n * CHUNK;

    for (int e = tid; e < 64 * 32; e += 256) {
        const int s = e >> 5;
        const int i = e & 31;
        const float ang = (float)s * sinv[i];
        float sn, c;
        sincosf(ang, &sn, &c);
        const size_t base = (size_t)(tokbase + s) * F_QKV + h * HEAD_D;
        const float q1 = g_qkv[base + i];
        const float q2 = g_qkv[base + 32 + i];
        qs[s * ATT_PAD + i]      =  q1 * c + q2 * sn;
        qs[s * ATT_PAD + 32 + i] = -q1 * sn + q2 * c;
        const float k1 = g_qkv[base + C_EMBD + i];
        const float k2 = g_qkv[base + C_EMBD + 32 + i];
        ks[s * ATT_PAD + i]      =  k1 * c + k2 * sn;
        ks[s * ATT_PAD + 32 + i] = -k1 * sn + k2 * c;
    }
    for (int e = tid; e < 64 * 64; e += 256) {
        const int s = e >> 6;
        const int dd = e & 63;
        vs[s * ATT_PAD + dd] =
            g_qkv[(size_t)(tokbase + s) * F_QKV + 2 * C_EMBD + h * HEAD_D + dd];
    }
    __syncthreads();

    {
        const int qrt = (tid >> 4) << 2;
        const int kct = (tid & 15) << 2;
        float acc[4][4];
#pragma unroll
        for (int r = 0; r < 4; r++)
#pragma unroll
            for (int c = 0; c < 4; c++) acc[r][c] = 0.0f;

        for (int i = 0; i < 64; i += 4) {
            float4 qv[4], kv[4];
#pragma unroll
            for (int r = 0; r < 4; r++)
                qv[r] = *(const float4*)&qs[(qrt + r) * ATT_PAD + i];
#pragma unroll
            for (int c = 0; c < 4; c++)
                kv[c] = *(const float4*)&ks[(kct + c) * ATT_PAD + i];
#pragma unroll
            for (int r = 0; r < 4; r++)
#pragma unroll
                for (int c = 0; c < 4; c++)
                    acc[r][c] += qv[r].x * kv[c].x + qv[r].y * kv[c].y +
                                 qv[r].z * kv[c].z + qv[r].w * kv[c].w;
        }
        const float scale = 0.125f;
#pragma unroll
        for (int r = 0; r < 4; r++)
            *(float4*)&ss[(qrt + r) * ATT_PAD + kct] =
                make_float4(acc[r][0] * scale, acc[r][1] * scale,
                            acc[r][2] * scale, acc[r][3] * scale);
    }
    __syncthreads();

    {
        const int row = tid >> 2;
        const int g = tid & 3;
        float loc[16];
        float m = -1e30f;
#pragma unroll
        for (int j = 0; j < 16; j++) {
            loc[j] = ss[row * ATT_PAD + g * 16 + j];
            m = fmaxf(m, loc[j]);
        }
        m = fmaxf(m, __shfl_xor_sync(0xffffffffu, m, 1));
        m = fmaxf(m, __shfl_xor_sync(0xffffffffu, m, 2));
        float sum = 0.0f;
#pragma unroll
        for (int j = 0; j < 16; j++) {
            loc[j] = __expf(loc[j] - m);
            sum += loc[j];
        }
        sum += __shfl_xor_sync(0xffffffffu, sum, 1);
        sum += __shfl_xor_sync(0xffffffffu, sum, 2);
        const float inv = 1.0f / sum;
#pragma unroll
        for (int j = 0; j < 16; j++)
            ss[row * ATT_PAD + g * 16 + j] = loc[j] * inv;
    }
    __syncthreads();

    {
        const int qrt = (tid >> 4) << 2;
        const int ddt = (tid & 15) << 2;
        float acc[4][4];
#pragma unroll
        for (int r = 0; r < 4; r++)
#pragma unroll
            for (int c = 0; c < 4; c++) acc[r][c] = 0.0f;

        for (int kc = 0; kc < 64; kc += 4) {
            float4 pv[4], vv[4];
#pragma unroll
            for (int r = 0; r < 4; r++)
                pv[r] = *(const float4*)&ss[(qrt + r) * ATT_PAD + kc];
#pragma unroll
            for (int m2 = 0; m2 < 4; m2++)
                vv[m2] = *(const float4*)&vs[(kc + m2) * ATT_PAD + ddt];
#pragma unroll
            for (int r = 0; r < 4; r++) {
                acc[r][0] += pv[r].x * vv[0].x + pv[r].y * vv[1].x +
                             pv[r].z * vv[2].x + pv[r].w * vv[3].x;
                acc[r][1] += pv[r].x * vv[0].y + pv[r].y * vv[1].y +
                             pv[r].z * vv[2].y + pv[r].w * vv[3].y;
                acc[r][2] += pv[r].x * vv[0].z + pv[r].y * vv[1].z +
                             pv[r].z * vv[2].z + pv[r].w * vv[3].z;
                acc[r][3] += pv[r].x * vv[0].w + pv[r].y * vv[1].w +
                             pv[r].z * vv[2].w + pv[r].w * vv[3].w;
            }
        }
#pragma unroll
        for (int r = 0; r < 4; r++)
            *(uint4*)&g_ya[(size_t)(tokbase + qrt + r) * C_EMBD + h * HEAD_D + ddt] =
                make_uint4(f2tf32(acc[r][0]), f2tf32(acc[r][1]),
                           f2tf32(acc[r][2]), f2tf32(acc[r][3]));
    }
}

// ----------------------------------------------------------------------------
extern "C" void kernel_launch(void* const* d_in, const int* in_sizes, int n_in,
                              void* d_out, int out_size) {
    const float* x      = (const float*)d_in[0];   // [4,4096,1024]
    const float* w_attn = (const float*)d_in[1];   // [3072,1024]
    const float* w_proj = (const float*)d_in[2];   // [1024,1024]
    float* out = (float*)d_out;                    // [4,4096,1024]

    float*    qkv = nullptr;
    uint32_t *xa = nullptr, *wa = nullptr, *wp = nullptr, *ya = nullptr;
    cudaGetSymbolAddress((void**)&qkv, g_qkv);
    cudaGetSymbolAddress((void**)&xa, g_xa);
    cudaGetSymbolAddress((void**)&wa, g_wa);
    cudaGetSymbolAddress((void**)&wp, g_wp);
    cudaGetSymbolAddress((void**)&ya, g_ya);

    cudaFuncSetAttribute(gemm_mma,
                         cudaFuncAttributeMaxDynamicSharedMemorySize,
                         G_SMEM_BYTES);
    cudaFuncSetAttribute(attn_kernel,
                         cudaFuncAttributeMaxDynamicSharedMemorySize,
                         ATT_SMEM_BYTES);

    dim3 blk(256);
    // fp32 -> tf32 pre-conversion
    const int n4x = M_TOK * C_EMBD / 4;
    const int n4a = F_QKV * C_EMBD / 4;
    const int n4p = C_EMBD * C_EMBD / 4;
    cvt_tf32<<<(n4x + 255) / 256, blk>>>((const float4*)x, (uint4*)xa, n4x);
    cvt_tf32<<<(n4a + 255) / 256, blk>>>((const float4*)w_attn, (uint4*)wa, n4a);
    cvt_tf32<<<(n4p + 255) / 256, blk>>>((const float4*)w_proj, (uint4*)wp, n4p);

    // qkv = x @ w_attn^T
    gemm_mma<<<dim3(F_QKV / BN, M_TOK / BM), blk, G_SMEM_BYTES>>>(
        xa, wa, qkv, F_QKV, C_EMBD);
    // per-chunk attention (RoPE fused), writes tf32 y
    attn_kernel<<<BATCH * (SEQ / CHUNK) * N_HEAD, blk, ATT_SMEM_BYTES>>>();
    // out = y @ w_proj^T
    gemm_mma<<<dim3(C_EMBD / BN, M_TOK / BM), blk, G_SMEM_BYTES>>>(
        ya, wp, out, C_EMBD, C_EMBD);
}